// round 1
// baseline (speedup 1.0000x reference)
#include <cuda_runtime.h>

// ---------------- problem constants ----------------
#define N_NODES 16384
#define N_EDGES 524288
#define BATCH   32
#define DIM     64
#define OUTD    64
#define FEAT    (BATCH * DIM)   /* 2048 */
#define NMAT    5
#define WROWS   (DIM * NMAT)    /* 320 */

// ---------------- device scratch (static: no allocations allowed) ----------
__device__ __align__(16) float g_x[NMAT][(size_t)N_NODES * FEAT];  // ~671 MB
__device__ float g_inv_drow[N_NODES];   // degree, then inverted in place
__device__ float g_inv_dcol[N_NODES];
__device__ int   g_cnt1[N_NODES];
__device__ int   g_cnt2[N_NODES];
__device__ int   g_rowptr1[N_NODES + 1];
__device__ int   g_rowptr2[N_NODES + 1];
__device__ int   g_pos1[N_NODES];
__device__ int   g_pos2[N_NODES];
__device__ int   g_adj_col[2][N_EDGES];
__device__ float g_adj_val[2][N_EDGES];

// ---------------- build kernels ----------------
__global__ void k_init() {
    int i = blockIdx.x * blockDim.x + threadIdx.x;
    if (i < N_NODES) {
        g_inv_drow[i] = 0.f;
        g_inv_dcol[i] = 0.f;
        g_cnt1[i] = 0;
        g_cnt2[i] = 0;
    }
}

__global__ void k_degree(const float* __restrict__ adj,
                         const int* __restrict__ rows,
                         const int* __restrict__ cols) {
    int e = blockIdx.x * blockDim.x + threadIdx.x;
    if (e < N_EDGES) {
        int r = rows[e], c = cols[e];
        float a = adj[e];
        atomicAdd(&g_inv_drow[r], a);
        atomicAdd(&g_inv_dcol[c], a);
        atomicAdd(&g_cnt1[c], 1);   // support1 CSR keyed by dst = cols
        atomicAdd(&g_cnt2[r], 1);   // support2 CSR keyed by dst = rows
    }
}

// single-block: invert degrees + exclusive scan both histograms
__global__ void k_scan() {
    __shared__ int sh[1024];
    int t = threadIdx.x;

    for (int i = t; i < N_NODES; i += 1024) {
        float d = g_inv_drow[i]; g_inv_drow[i] = (d > 0.f) ? (1.f / d) : 0.f;
        float c = g_inv_dcol[i]; g_inv_dcol[i] = (c > 0.f) ? (1.f / c) : 0.f;
    }
    __syncthreads();

    // ---- scan cnt1 -> rowptr1/pos1 ----
    {
        int base = t * 16;
        int local[16];
        int s = 0;
        #pragma unroll
        for (int i = 0; i < 16; i++) { local[i] = s; s += g_cnt1[base + i]; }
        sh[t] = s;
        __syncthreads();
        for (int off = 1; off < 1024; off <<= 1) {
            int v = (t >= off) ? sh[t - off] : 0;
            __syncthreads();
            sh[t] += v;
            __syncthreads();
        }
        int prev = t ? sh[t - 1] : 0;
        #pragma unroll
        for (int i = 0; i < 16; i++) {
            int p = prev + local[i];
            g_rowptr1[base + i] = p;
            g_pos1[base + i] = p;
        }
        if (t == 1023) g_rowptr1[N_NODES] = sh[1023];
        __syncthreads();
    }
    // ---- scan cnt2 -> rowptr2/pos2 ----
    {
        int base = t * 16;
        int local[16];
        int s = 0;
        #pragma unroll
        for (int i = 0; i < 16; i++) { local[i] = s; s += g_cnt2[base + i]; }
        sh[t] = s;
        __syncthreads();
        for (int off = 1; off < 1024; off <<= 1) {
            int v = (t >= off) ? sh[t - off] : 0;
            __syncthreads();
            sh[t] += v;
            __syncthreads();
        }
        int prev = t ? sh[t - 1] : 0;
        #pragma unroll
        for (int i = 0; i < 16; i++) {
            int p = prev + local[i];
            g_rowptr2[base + i] = p;
            g_pos2[base + i] = p;
        }
        if (t == 1023) g_rowptr2[N_NODES] = sh[1023];
    }
}

__global__ void k_fill(const float* __restrict__ adj,
                       const int* __restrict__ rows,
                       const int* __restrict__ cols) {
    int e = blockIdx.x * blockDim.x + threadIdx.x;
    if (e < N_EDGES) {
        int r = rows[e], c = cols[e];
        float a = adj[e];
        // support1: y[cols] += (a * inv_drow[rows]) * x[rows]
        int s1 = atomicAdd(&g_pos1[c], 1);
        g_adj_col[0][s1] = r;
        g_adj_val[0][s1] = a * g_inv_drow[r];
        // support2: y[rows] += (a * inv_dcol[cols]) * x[cols]
        int s2 = atomicAdd(&g_pos2[r], 1);
        g_adj_col[1][s2] = c;
        g_adj_val[1][s2] = a * g_inv_dcol[c];
    }
}

// x0[n, b*64+d] = inputs[b, n, d]   (feature layout chosen so GEMM rows are contiguous)
__global__ void k_transpose(const float* __restrict__ in) {
    int idx = blockIdx.x * blockDim.x + threadIdx.x;   // over N*FEAT/4
    int f4 = idx & 511;
    int n  = idx >> 9;
    int f  = f4 << 2;
    int b  = f >> 6;
    int d  = f & 63;
    float4 v = *reinterpret_cast<const float4*>(
        in + ((size_t)b * N_NODES * DIM + (size_t)n * DIM + d));
    *reinterpret_cast<float4*>(&g_x[0][(size_t)n * FEAT + f]) = v;
}

// ---------------- SpMM (CSR gather, feature-chunk-major for L2 residency) ----
// out = (S @ xin)            if m_z < 0
// out = 2*(S @ xin) - xz     otherwise
__global__ void __launch_bounds__(128)
k_spmm(int support, int m_in, int m_z, int m_out) {
    const int* __restrict__ rowptr = support ? g_rowptr2 : g_rowptr1;
    const int* __restrict__ colidx = g_adj_col[support];
    const float* __restrict__ val  = g_adj_val[support];
    const float* __restrict__ xin  = g_x[m_in];
    float* __restrict__ xout       = g_x[m_out];

    int n = blockIdx.x;
    int fbase = (blockIdx.y << 9) + (threadIdx.x << 2);

    int e   = rowptr[n];
    int end = rowptr[n + 1];

    float4 a0 = make_float4(0.f, 0.f, 0.f, 0.f);
    float4 a1 = make_float4(0.f, 0.f, 0.f, 0.f);

    for (; e + 2 <= end; e += 2) {
        int   c0 = colidx[e],   c1 = colidx[e + 1];
        float v0 = val[e],      v1 = val[e + 1];
        float4 x0 = *reinterpret_cast<const float4*>(xin + (size_t)c0 * FEAT + fbase);
        float4 x1 = *reinterpret_cast<const float4*>(xin + (size_t)c1 * FEAT + fbase);
        a0.x += v0 * x0.x; a0.y += v0 * x0.y; a0.z += v0 * x0.z; a0.w += v0 * x0.w;
        a1.x += v1 * x1.x; a1.y += v1 * x1.y; a1.z += v1 * x1.z; a1.w += v1 * x1.w;
    }
    if (e < end) {
        int   c0 = colidx[e];
        float v0 = val[e];
        float4 x0 = *reinterpret_cast<const float4*>(xin + (size_t)c0 * FEAT + fbase);
        a0.x += v0 * x0.x; a0.y += v0 * x0.y; a0.z += v0 * x0.z; a0.w += v0 * x0.w;
    }
    a0.x += a1.x; a0.y += a1.y; a0.z += a1.z; a0.w += a1.w;

    size_t ooff = (size_t)n * FEAT + fbase;
    if (m_z >= 0) {
        const float* __restrict__ xz = g_x[m_z];
        float4 z = *reinterpret_cast<const float4*>(xz + ooff);
        a0.x = 2.f * a0.x - z.x;
        a0.y = 2.f * a0.y - z.y;
        a0.z = 2.f * a0.z - z.z;
        a0.w = 2.f * a0.w - z.w;
    }
    *reinterpret_cast<float4*>(xout + ooff) = a0;
}

// ---------------- fused output GEMM: out[b,n,:] = sum_{d,m} x_m[n, b*64+d] * W[d*5+m, :]
__global__ void __launch_bounds__(256, 2)
k_gemm(const float* __restrict__ W, const float* __restrict__ bias,
       float* __restrict__ out) {
    extern __shared__ float sw[];   // WROWS*OUTD floats (80 KB)
    __shared__ float sb[OUTD];

    for (int i = threadIdx.x; i < WROWS * OUTD; i += 256) sw[i] = W[i];
    if (threadIdx.x < OUTD) sb[threadIdx.x] = bias[threadIdx.x];
    __syncthreads();

    int row = blockIdx.x * 256 + threadIdx.x;  // row = b*N + n
    int b = row >> 14;        // / 16384
    int n = row & 16383;
    const int off = n * FEAT + b * DIM;

    float acc[OUTD];
    #pragma unroll
    for (int o = 0; o < OUTD; o++) acc[o] = sb[o];

    #pragma unroll 1
    for (int d4 = 0; d4 < 16; ++d4) {
        float4 xv[NMAT];
        #pragma unroll
        for (int m = 0; m < NMAT; m++)
            xv[m] = *reinterpret_cast<const float4*>(&g_x[m][(size_t)off + d4 * 4]);
        #pragma unroll
        for (int j = 0; j < 4; j++) {
            int d = d4 * 4 + j;
            #pragma unroll
            for (int m = 0; m < NMAT; m++) {
                float x = (j == 0) ? xv[m].x : (j == 1) ? xv[m].y
                        : (j == 2) ? xv[m].z : xv[m].w;
                const float4* wrow =
                    reinterpret_cast<const float4*>(sw + (d * NMAT + m) * OUTD);
                #pragma unroll
                for (int o4 = 0; o4 < 16; o4++) {
                    float4 w = wrow[o4];
                    acc[o4 * 4 + 0] += x * w.x;
                    acc[o4 * 4 + 1] += x * w.y;
                    acc[o4 * 4 + 2] += x * w.z;
                    acc[o4 * 4 + 3] += x * w.w;
                }
            }
        }
    }

    float4* op = reinterpret_cast<float4*>(out + (size_t)row * OUTD);
    #pragma unroll
    for (int o4 = 0; o4 < 16; o4++)
        op[o4] = make_float4(acc[o4 * 4], acc[o4 * 4 + 1],
                             acc[o4 * 4 + 2], acc[o4 * 4 + 3]);
}

// ---------------- launch ----------------
extern "C" void kernel_launch(void* const* d_in, const int* in_sizes, int n_in,
                              void* d_out, int out_size) {
    const float* inputs  = (const float*)d_in[0];
    const float* adj     = (const float*)d_in[1];
    const int*   rows    = (const int*)d_in[2];
    const int*   cols    = (const int*)d_in[3];
    const float* weights = (const float*)d_in[4];
    const float* biases  = (const float*)d_in[5];
    float*       out     = (float*)d_out;

    cudaFuncSetAttribute(k_gemm, cudaFuncAttributeMaxDynamicSharedMemorySize,
                         WROWS * OUTD * (int)sizeof(float));

    k_init<<<(N_NODES + 255) / 256, 256>>>();
    k_degree<<<N_EDGES / 256, 256>>>(adj, rows, cols);
    k_scan<<<1, 1024>>>();
    k_fill<<<N_EDGES / 256, 256>>>(adj, rows, cols);
    k_transpose<<<(N_NODES * FEAT / 4) / 256, 256>>>(inputs);

    dim3 sgrid(N_NODES, FEAT / 512);
    // xs[1] = S1 @ x0
    k_spmm<<<sgrid, 128>>>(0, 0, -1, 1);
    // xs[2] = 2*S1@xs[1] - x0
    k_spmm<<<sgrid, 128>>>(0, 1, 0, 2);
    // xs[3] = S2 @ xs[1]   (x0 deliberately not reset between supports)
    k_spmm<<<sgrid, 128>>>(1, 1, -1, 3);
    // xs[4] = 2*S2@xs[3] - xs[1]
    k_spmm<<<sgrid, 128>>>(1, 3, 1, 4);

    k_gemm<<<(BATCH * N_NODES) / 256, 256, WROWS * OUTD * sizeof(float)>>>(
        weights, biases, out);
}